// round 1
// baseline (speedup 1.0000x reference)
#include <cuda_runtime.h>
#include <cstdint>
#include <cstdio>

// Problem constants
#define BB 2
#define LL 2048
#define NH 32
#define HD 128
#define CC 4096           // NH*HD
#define MM (BB*LL)        // 4096 rows of x
#define KK CC             // 4096 reduction dim

// ---------------------------------------------------------------------------
// Scratch (device globals; allocation is forbidden at runtime)
// ---------------------------------------------------------------------------
__device__ float g_q[(size_t)BB * NH * LL * HD];   // [B,H,L,HD]
__device__ float g_k[(size_t)BB * NH * LL * HD];
__device__ float g_v[(size_t)BB * NH * LL * HD];
__device__ float g_att[(size_t)BB * LL * CC];      // [B,L,C]

// ---------------------------------------------------------------------------
// tf32 helpers
// ---------------------------------------------------------------------------
__device__ __forceinline__ unsigned f2tf32(float x) {
    unsigned r;
    asm("cvt.rna.tf32.f32 %0, %1;" : "=r"(r) : "f"(x));
    return r;
}

__device__ __forceinline__ void mma_tf32(float c[4], const unsigned a[4], const unsigned b[2]) {
    asm volatile(
        "mma.sync.aligned.m16n8k8.row.col.f32.tf32.tf32.f32 "
        "{%0,%1,%2,%3}, {%4,%5,%6,%7}, {%8,%9}, {%0,%1,%2,%3};\n"
        : "+f"(c[0]), "+f"(c[1]), "+f"(c[2]), "+f"(c[3])
        : "r"(a[0]), "r"(a[1]), "r"(a[2]), "r"(a[3]), "r"(b[0]), "r"(b[1]));
}

// ---------------------------------------------------------------------------
// GEMM: C[M,N] = A[M,K] * W[N,K]^T, tf32 mma, 128x128x32 block tiles
// mode 0: A = x, z = blockIdx.z picks (wq,wk,wv); epilogue applies RoPE on q,k
//         and writes to g_q/g_k/g_v in [B,H,L,HD].
// mode 1: A = g_att, W = wo, writes fp32 to proj_out row-major [M,C].
// ---------------------------------------------------------------------------
__global__ __launch_bounds__(256) void gemm_kernel(
    const float* __restrict__ A,
    const float* __restrict__ Wq,
    const float* __restrict__ Wk,
    const float* __restrict__ Wv,
    const float* __restrict__ rope,
    float* __restrict__ proj_out,
    int mode)
{
    __shared__ unsigned As[128][36];   // pad ld=36 (==4 mod 32): conflict-free frag loads
    __shared__ unsigned Bs[128][36];

    const int tid  = threadIdx.x;
    const int lane = tid & 31;
    const int warp = tid >> 5;
    const int g    = lane >> 2;     // group id (row within 16-row frag)
    const int t    = lane & 3;      // thread-in-group (k / col pair index)
    const int wm   = warp & 3;      // 4 warps along M (32 rows each)
    const int wn   = warp >> 2;     // 2 warps along N (64 cols each)

    const int bm = blockIdx.y * 128;
    const int bn = blockIdx.x * 128;
    const int z  = blockIdx.z;

    const float* Ap = (mode == 0) ? A : (const float*)g_att;
    const float* W  = (mode == 0) ? (z == 0 ? Wq : (z == 1 ? Wk : Wv)) : Wq;
    float* qkv_out  = (z == 0) ? g_q : (z == 1 ? g_k : g_v);

    float acc[2][8][4];
    #pragma unroll
    for (int i = 0; i < 2; i++)
        #pragma unroll
        for (int j = 0; j < 8; j++)
            #pragma unroll
            for (int r = 0; r < 4; r++) acc[i][j][r] = 0.f;

    const int lr = tid >> 3;         // 0..31 load row
    const int lc = (tid & 7) * 4;    // 0..28 load col (float4)

    for (int k0 = 0; k0 < KK; k0 += 32) {
        #pragma unroll
        for (int r = 0; r < 4; r++) {
            int row = lr + r * 32;
            float4 av = *(const float4*)(Ap + (size_t)(bm + row) * KK + k0 + lc);
            As[row][lc + 0] = f2tf32(av.x);
            As[row][lc + 1] = f2tf32(av.y);
            As[row][lc + 2] = f2tf32(av.z);
            As[row][lc + 3] = f2tf32(av.w);
            float4 bv = *(const float4*)(W + (size_t)(bn + row) * KK + k0 + lc);
            Bs[row][lc + 0] = f2tf32(bv.x);
            Bs[row][lc + 1] = f2tf32(bv.y);
            Bs[row][lc + 2] = f2tf32(bv.z);
            Bs[row][lc + 3] = f2tf32(bv.w);
        }
        __syncthreads();

        #pragma unroll
        for (int kk = 0; kk < 32; kk += 8) {
            unsigned af[2][4];
            #pragma unroll
            for (int mf = 0; mf < 2; mf++) {
                int mb = wm * 32 + mf * 16;
                af[mf][0] = As[mb + g][kk + t];
                af[mf][1] = As[mb + g + 8][kk + t];
                af[mf][2] = As[mb + g][kk + t + 4];
                af[mf][3] = As[mb + g + 8][kk + t + 4];
            }
            unsigned bf[8][2];
            #pragma unroll
            for (int nf = 0; nf < 8; nf++) {
                int nb = wn * 64 + nf * 8;
                bf[nf][0] = Bs[nb + g][kk + t];
                bf[nf][1] = Bs[nb + g][kk + t + 4];
            }
            #pragma unroll
            for (int mf = 0; mf < 2; mf++)
                #pragma unroll
                for (int nf = 0; nf < 8; nf++)
                    mma_tf32(acc[mf][nf], af[mf], bf[nf]);
        }
        __syncthreads();
    }

    // Epilogue
    #pragma unroll
    for (int mf = 0; mf < 2; mf++) {
        #pragma unroll
        for (int nf = 0; nf < 8; nf++) {
            int m0 = bm + wm * 32 + mf * 16 + g;
            int n0 = bn + wn * 64 + nf * 8 + 2 * t;
            #pragma unroll
            for (int rr = 0; rr < 2; rr++) {
                int m = m0 + rr * 8;
                float v0 = acc[mf][nf][rr * 2 + 0];
                float v1 = acc[mf][nf][rr * 2 + 1];
                if (mode == 0) {
                    int b  = m >> 11;       // / 2048
                    int l  = m & 2047;
                    int h  = n0 >> 7;       // / 128
                    int dh = n0 & 127;
                    if (z < 2) {            // RoPE on q and k; (dh even, dh+1) pair in-thread
                        int pair = dh >> 1;
                        float cs = rope[(l * 64 + pair) * 2 + 0];
                        float sn = rope[(l * 64 + pair) * 2 + 1];
                        float re = v0 * cs - v1 * sn;
                        float im = v1 * cs + v0 * sn;
                        v0 = re; v1 = im;
                    }
                    size_t idx = ((size_t)(b * NH + h) * LL + l) * HD + dh;
                    qkv_out[idx]     = v0;
                    qkv_out[idx + 1] = v1;
                } else {
                    proj_out[(size_t)m * CC + n0]     = v0;
                    proj_out[(size_t)m * CC + n0 + 1] = v1;
                }
            }
        }
    }
}

// ---------------------------------------------------------------------------
// Flash attention: per (b, h, 64-row q tile). tf32 mma for S=QK^T and O=PV.
// ---------------------------------------------------------------------------
#define QLD 132   // 128 + 4  (ld % 32 == 4 -> conflict-free frag loads)
#define PLD 68    // 64 + 4

#define ATT_SMEM ((64*QLD + 64*QLD + 128*PLD) * 4 + 64*PLD*4 + 3*64*4)

__global__ __launch_bounds__(256) void attn_kernel()
{
    extern __shared__ unsigned char sm_raw[];
    unsigned* Qs  = (unsigned*)sm_raw;          // [64][132] tf32
    unsigned* Ks  = Qs + 64 * QLD;              // [64][132] tf32
    unsigned* Vts = Ks + 64 * QLD;              // [128][68] tf32 (V transposed: [d][kv])
    float*    Ps  = (float*)(Vts + 128 * PLD);  // [64][68] raw S, then tf32 P bits
    float*    m_s = Ps + 64 * PLD;
    float*    l_s = m_s + 64;
    float*    al_s = l_s + 64;

    const int tid  = threadIdx.x;
    const int lane = tid & 31;
    const int warp = tid >> 5;
    const int g    = lane >> 2;
    const int t    = lane & 3;
    const int wm   = warp & 3;      // rows: wm*16 .. +15
    const int wn   = warp >> 2;     // S cols: wn*32..; O cols: wn*64..
    const int mBase = wm * 16;

    const int qt = blockIdx.x, h = blockIdx.y, b = blockIdx.z;
    const int q0 = qt * 64;

    const float* Qg = g_q + (size_t)(b * NH + h) * LL * HD;
    const float* Kg = g_k + (size_t)(b * NH + h) * LL * HD;
    const float* Vg = g_v + (size_t)(b * NH + h) * LL * HD;

    // Load Q tile (64 x 128)
    #pragma unroll
    for (int i = 0; i < 8; i++) {
        int idx = tid + i * 256;            // float4 index over 64*32
        int row = idx >> 5;
        int c4  = (idx & 31) << 2;
        float4 v = *(const float4*)(Qg + (size_t)(q0 + row) * HD + c4);
        unsigned* d = Qs + row * QLD + c4;
        d[0] = f2tf32(v.x); d[1] = f2tf32(v.y); d[2] = f2tf32(v.z); d[3] = f2tf32(v.w);
    }
    if (tid < 64) { m_s[tid] = -1e30f; l_s[tid] = 0.f; }

    float o[8][4];
    #pragma unroll
    for (int nf = 0; nf < 8; nf++)
        #pragma unroll
        for (int r = 0; r < 4; r++) o[nf][r] = 0.f;

    const int ntiles = qt + 1;   // causal: kv tiles 0..qt
    for (int kt = 0; kt < ntiles; kt++) {
        int kv0 = kt * 64;
        // Load K tile and V tile (V stored transposed)
        #pragma unroll
        for (int i = 0; i < 8; i++) {
            int idx = tid + i * 256;
            int row = idx >> 5;
            int c4  = (idx & 31) << 2;
            float4 kv = *(const float4*)(Kg + (size_t)(kv0 + row) * HD + c4);
            unsigned* d = Ks + row * QLD + c4;
            d[0] = f2tf32(kv.x); d[1] = f2tf32(kv.y); d[2] = f2tf32(kv.z); d[3] = f2tf32(kv.w);
            float4 vv = *(const float4*)(Vg + (size_t)(kv0 + row) * HD + c4);
            Vts[(c4 + 0) * PLD + row] = f2tf32(vv.x);
            Vts[(c4 + 1) * PLD + row] = f2tf32(vv.y);
            Vts[(c4 + 2) * PLD + row] = f2tf32(vv.z);
            Vts[(c4 + 3) * PLD + row] = f2tf32(vv.w);
        }
        __syncthreads();

        // S = Q K^T : warp tile 16 x 32
        float s[4][4];
        #pragma unroll
        for (int nf = 0; nf < 4; nf++)
            #pragma unroll
            for (int r = 0; r < 4; r++) s[nf][r] = 0.f;

        #pragma unroll
        for (int k = 0; k < 128; k += 8) {
            unsigned af[4];
            af[0] = Qs[(mBase + g) * QLD + k + t];
            af[1] = Qs[(mBase + g + 8) * QLD + k + t];
            af[2] = Qs[(mBase + g) * QLD + k + t + 4];
            af[3] = Qs[(mBase + g + 8) * QLD + k + t + 4];
            #pragma unroll
            for (int nf = 0; nf < 4; nf++) {
                int nb = wn * 32 + nf * 8;
                unsigned bf[2];
                bf[0] = Ks[(nb + g) * QLD + k + t];
                bf[1] = Ks[(nb + g) * QLD + k + t + 4];
                mma_tf32(s[nf], af, bf);
            }
        }

        // scale + causal mask + store raw S to smem
        const float sc = 0.08838834764831845f;   // 1/sqrt(128)
        #pragma unroll
        for (int nf = 0; nf < 4; nf++) {
            int nb = wn * 32 + nf * 8 + 2 * t;
            #pragma unroll
            for (int rr = 0; rr < 2; rr++) {
                int r    = mBase + g + rr * 8;
                int grow = q0 + r;
                #pragma unroll
                for (int cc = 0; cc < 2; cc++) {
                    int col = kv0 + nb + cc;
                    float v = s[nf][rr * 2 + cc] * sc;
                    if (col > grow) v = -1e30f;
                    Ps[r * PLD + nb + cc] = v;
                }
            }
        }
        __syncthreads();

        // Online softmax: warp w owns rows w*8 .. w*8+7; 2 cols/lane
        #pragma unroll
        for (int i = 0; i < 8; i++) {
            int r = warp * 8 + i;
            float v0 = Ps[r * PLD + lane];
            float v1 = Ps[r * PLD + lane + 32];
            float mx = fmaxf(v0, v1);
            #pragma unroll
            for (int off = 16; off; off >>= 1) mx = fmaxf(mx, __shfl_xor_sync(0xffffffffu, mx, off));
            float mold = m_s[r];
            float mnew = fmaxf(mold, mx);
            float al = __expf(mold - mnew);
            float p0 = __expf(v0 - mnew);
            float p1 = __expf(v1 - mnew);
            float sum = p0 + p1;
            #pragma unroll
            for (int off = 16; off; off >>= 1) sum += __shfl_xor_sync(0xffffffffu, sum, off);
            ((unsigned*)Ps)[r * PLD + lane]      = f2tf32(p0);
            ((unsigned*)Ps)[r * PLD + lane + 32] = f2tf32(p1);
            if (lane == 0) {
                l_s[r] = al * l_s[r] + sum;
                m_s[r] = mnew;
                al_s[r] = al;
            }
        }
        __syncthreads();

        // Rescale O, then O += P V  (warp tile 16 x 64)
        float a0 = al_s[mBase + g];
        float a1 = al_s[mBase + g + 8];
        #pragma unroll
        for (int nf = 0; nf < 8; nf++) {
            o[nf][0] *= a0; o[nf][1] *= a0;
            o[nf][2] *= a1; o[nf][3] *= a1;
        }
        const unsigned* Pu = (const unsigned*)Ps;
        #pragma unroll
        for (int k = 0; k < 64; k += 8) {
            unsigned af[4];
            af[0] = Pu[(mBase + g) * PLD + k + t];
            af[1] = Pu[(mBase + g + 8) * PLD + k + t];
            af[2] = Pu[(mBase + g) * PLD + k + t + 4];
            af[3] = Pu[(mBase + g + 8) * PLD + k + t + 4];
            #pragma unroll
            for (int nf = 0; nf < 8; nf++) {
                int nb = wn * 64 + nf * 8;
                unsigned bf[2];
                bf[0] = Vts[(nb + g) * PLD + k + t];
                bf[1] = Vts[(nb + g) * PLD + k + t + 4];
                mma_tf32(o[nf], af, bf);
            }
        }
        __syncthreads();
    }

    // Finalize: O /= l, write to g_att in [B,L,C] layout (ready for out-proj GEMM)
    float li0 = 1.f / l_s[mBase + g];
    float li1 = 1.f / l_s[mBase + g + 8];
    #pragma unroll
    for (int nf = 0; nf < 8; nf++) {
        int col = h * HD + wn * 64 + nf * 8 + 2 * t;
        int r0  = q0 + mBase + g;
        int r1  = r0 + 8;
        size_t i0 = ((size_t)(b * LL + r0)) * CC + col;
        size_t i1 = ((size_t)(b * LL + r1)) * CC + col;
        g_att[i0]     = o[nf][0] * li0;
        g_att[i0 + 1] = o[nf][1] * li0;
        g_att[i1]     = o[nf][2] * li1;
        g_att[i1 + 1] = o[nf][3] * li1;
    }
}

// ---------------------------------------------------------------------------
// Launch
// ---------------------------------------------------------------------------
extern "C" void kernel_launch(void* const* d_in, const int* in_sizes, int n_in,
                              void* d_out, int out_size)
{
    (void)in_sizes; (void)out_size;
    // metadata order: x, rope, mask, max_seq_length, wq, wk, wv, wo.
    // Weights addressed from the tail for robustness to scalar/mask handling.
    const float* x    = (const float*)d_in[0];
    const float* rope = (const float*)d_in[1];
    const float* wq   = (const float*)d_in[n_in - 4];
    const float* wk   = (const float*)d_in[n_in - 3];
    const float* wv   = (const float*)d_in[n_in - 2];
    const float* wo   = (const float*)d_in[n_in - 1];
    float* out = (float*)d_out;

    cudaFuncSetAttribute(attn_kernel, cudaFuncAttributeMaxDynamicSharedMemorySize, ATT_SMEM);

    dim3 blk(256);
    // 1) QKV projections + RoPE
    gemm_kernel<<<dim3(CC / 128, MM / 128, 3), blk>>>(x, wq, wk, wv, rope, nullptr, 0);
    // 2) Causal flash attention
    attn_kernel<<<dim3(LL / 64, NH, BB), blk, ATT_SMEM>>>();
    // 3) Output projection
    gemm_kernel<<<dim3(CC / 128, MM / 128, 1), blk>>>(nullptr, wo, nullptr, nullptr, nullptr, out, 1);
}

// round 2
// speedup vs baseline: 1.4637x; 1.4637x over previous
#include <cuda_runtime.h>
#include <cstdint>

// Problem constants
#define BB 2
#define LL 2048
#define NH 32
#define HD 128
#define CC 4096           // NH*HD
#define MM (BB*LL)        // 4096 rows of x
#define KK CC             // 4096 reduction dim

// ---------------------------------------------------------------------------
// Scratch (device globals; runtime allocation forbidden). All tf32 bit arrays.
// ---------------------------------------------------------------------------
__device__ unsigned g_xt[(size_t)MM * KK];            // x in tf32 bits
__device__ unsigned g_wq[(size_t)CC * KK];
__device__ unsigned g_wk[(size_t)CC * KK];
__device__ unsigned g_wv[(size_t)CC * KK];
__device__ unsigned g_wo[(size_t)CC * KK];
__device__ unsigned g_q[(size_t)BB * NH * LL * HD];   // [B,H,L,HD] tf32 bits
__device__ unsigned g_k[(size_t)BB * NH * LL * HD];
__device__ unsigned g_v[(size_t)BB * NH * LL * HD];
__device__ unsigned g_att[(size_t)BB * LL * CC];      // [B,L,C] tf32 bits

// ---------------------------------------------------------------------------
// helpers
// ---------------------------------------------------------------------------
__device__ __forceinline__ unsigned f2tf32(float x) {
    unsigned r;
    asm("cvt.rna.tf32.f32 %0, %1;" : "=r"(r) : "f"(x));
    return r;
}

__device__ __forceinline__ void mma_tf32(float c[4], const unsigned a[4], const unsigned b[2]) {
    asm volatile(
        "mma.sync.aligned.m16n8k8.row.col.f32.tf32.tf32.f32 "
        "{%0,%1,%2,%3}, {%4,%5,%6,%7}, {%8,%9}, {%0,%1,%2,%3};\n"
        : "+f"(c[0]), "+f"(c[1]), "+f"(c[2]), "+f"(c[3])
        : "r"(a[0]), "r"(a[1]), "r"(a[2]), "r"(a[3]), "r"(b[0]), "r"(b[1]));
}

__device__ __forceinline__ void cp16(unsigned* sdst, const unsigned* gsrc) {
    unsigned sa = (unsigned)__cvta_generic_to_shared(sdst);
    asm volatile("cp.async.cg.shared.global [%0], [%1], 16;" :: "r"(sa), "l"(gsrc));
}
#define CP_COMMIT() asm volatile("cp.async.commit_group;")
#define CP_WAIT(N)  asm volatile("cp.async.wait_group %0;" :: "n"(N))

// ---------------------------------------------------------------------------
// Convert fp32 -> tf32 bits (elementwise, vectorized)
// ---------------------------------------------------------------------------
__global__ __launch_bounds__(256) void cvt_kernel(const float* __restrict__ s,
                                                  unsigned* __restrict__ d, int n4)
{
    int i = blockIdx.x * blockDim.x + threadIdx.x;
    if (i < n4) {
        float4 v = ((const float4*)s)[i];
        uint4 u;
        u.x = f2tf32(v.x); u.y = f2tf32(v.y); u.z = f2tf32(v.z); u.w = f2tf32(v.w);
        ((uint4*)d)[i] = u;
    }
}

// ---------------------------------------------------------------------------
// GEMM: C[M,N] = A[M,K] * W[N,K]^T, tf32 mma, 256x128 block tile, 64x64/warp,
// 3-stage cp.async pipeline. mode 0: z picks wq/wk/wv, RoPE epilogue -> g_q/k/v.
// mode 1: A = g_att, W = g_wo, fp32 output.
// ---------------------------------------------------------------------------
#define GEMM_STAGE_W (256*36 + 128*36)   // words per stage: 13824
#define GEMM_SMEM (3 * GEMM_STAGE_W * 4) // 165888 bytes

__global__ __launch_bounds__(256) void gemm_kernel(
    const unsigned* __restrict__ Ag,
    const float* __restrict__ rope,
    float* __restrict__ out_f,
    int mode)
{
    extern __shared__ unsigned sm[];

    const int tid  = threadIdx.x;
    const int lane = tid & 31;
    const int warp = tid >> 5;
    const int g    = lane >> 2;
    const int t    = lane & 3;
    const int wm   = warp & 3;      // 4 warps along M (64 rows each)
    const int wn   = warp >> 2;     // 2 warps along N (64 cols each)

    const int bm = blockIdx.y * 256;
    const int bn = blockIdx.x * 128;
    const int z  = blockIdx.z;

    const unsigned* W = (mode == 1) ? g_wo : (z == 0 ? g_wq : (z == 1 ? g_wk : g_wv));
    unsigned* qkv_out = (z == 0) ? g_q : (z == 1 ? g_k : g_v);

    float acc[4][8][4];
    #pragma unroll
    for (int i = 0; i < 4; i++)
        #pragma unroll
        for (int j = 0; j < 8; j++)
            #pragma unroll
            for (int r = 0; r < 4; r++) acc[i][j][r] = 0.f;

    const int lr = tid >> 3;        // 0..31
    const int lc = (tid & 7) * 4;   // 0..28

    // issue loads for one stage
    auto issue = [&](int stage, int k0) {
        unsigned* As = sm + stage * GEMM_STAGE_W;
        unsigned* Bs = As + 256 * 36;
        #pragma unroll
        for (int i = 0; i < 8; i++) {
            int row = lr + i * 32;
            cp16(As + row * 36 + lc, Ag + (size_t)(bm + row) * KK + k0 + lc);
        }
        #pragma unroll
        for (int i = 0; i < 4; i++) {
            int row = lr + i * 32;
            cp16(Bs + row * 36 + lc, W + (size_t)(bn + row) * KK + k0 + lc);
        }
    };

    const int NT = KK / 32;   // 128
    issue(0, 0);  CP_COMMIT();
    issue(1, 32); CP_COMMIT();

    for (int kt = 0; kt < NT; kt++) {
        CP_WAIT(1);
        __syncthreads();
        if (kt + 2 < NT) issue((kt + 2) % 3, (kt + 2) * 32);
        CP_COMMIT();

        const unsigned* As = sm + (kt % 3) * GEMM_STAGE_W;
        const unsigned* Bs = As + 256 * 36;

        #pragma unroll
        for (int kk = 0; kk < 32; kk += 8) {
            unsigned af[4][4];
            #pragma unroll
            for (int mf = 0; mf < 4; mf++) {
                int mb = wm * 64 + mf * 16;
                af[mf][0] = As[(mb + g)     * 36 + kk + t];
                af[mf][1] = As[(mb + g + 8) * 36 + kk + t];
                af[mf][2] = As[(mb + g)     * 36 + kk + t + 4];
                af[mf][3] = As[(mb + g + 8) * 36 + kk + t + 4];
            }
            unsigned bf[8][2];
            #pragma unroll
            for (int nf = 0; nf < 8; nf++) {
                int nb = wn * 64 + nf * 8;
                bf[nf][0] = Bs[(nb + g) * 36 + kk + t];
                bf[nf][1] = Bs[(nb + g) * 36 + kk + t + 4];
            }
            #pragma unroll
            for (int mf = 0; mf < 4; mf++)
                #pragma unroll
                for (int nf = 0; nf < 8; nf++)
                    mma_tf32(acc[mf][nf], af[mf], bf[nf]);
        }
    }

    // Epilogue
    #pragma unroll
    for (int mf = 0; mf < 4; mf++) {
        #pragma unroll
        for (int nf = 0; nf < 8; nf++) {
            int m0 = bm + wm * 64 + mf * 16 + g;
            int n0 = bn + wn * 64 + nf * 8 + 2 * t;
            #pragma unroll
            for (int rr = 0; rr < 2; rr++) {
                int m = m0 + rr * 8;
                float v0 = acc[mf][nf][rr * 2 + 0];
                float v1 = acc[mf][nf][rr * 2 + 1];
                if (mode == 0) {
                    int b  = m >> 11;
                    int l  = m & 2047;
                    int h  = n0 >> 7;
                    int dh = n0 & 127;
                    if (z < 2) {
                        int pair = dh >> 1;
                        float cs = rope[(l * 64 + pair) * 2 + 0];
                        float sn = rope[(l * 64 + pair) * 2 + 1];
                        float re = v0 * cs - v1 * sn;
                        float im = v1 * cs + v0 * sn;
                        v0 = re; v1 = im;
                    }
                    size_t idx = ((size_t)(b * NH + h) * LL + l) * HD + dh;
                    qkv_out[idx]     = f2tf32(v0);
                    qkv_out[idx + 1] = f2tf32(v1);
                } else {
                    out_f[(size_t)m * CC + n0]     = v0;
                    out_f[(size_t)m * CC + n0 + 1] = v1;
                }
            }
        }
    }
}

// ---------------------------------------------------------------------------
// Flash attention: (b, h, 64-row q tile). tf32 operands preconverted in gmem.
// cp.async double-buffered K/V. V row-major with ld=136 (conflict-free column
// fragment reads for O = P*V).
// ---------------------------------------------------------------------------
#define QLD 132   // ld % 32 == 4: conflict-free row fragment loads
#define VLD 136   // ld % 32 == 8: conflict-free column fragment loads
#define PLD 68

#define ATT_SMEM ((64*QLD + 2*64*QLD + 2*64*VLD + 64*PLD + 3*64) * 4)

__global__ __launch_bounds__(256) void attn_kernel()
{
    extern __shared__ unsigned sm[];
    unsigned* Qs   = sm;                     // [64][132]
    unsigned* Ks   = Qs + 64 * QLD;          // 2 x [64][132]
    unsigned* Vs   = Ks + 2 * 64 * QLD;      // 2 x [64][136]
    float*    Ps   = (float*)(Vs + 2 * 64 * VLD);  // [64][68]
    float*    m_s  = Ps + 64 * PLD;
    float*    l_s  = m_s + 64;
    float*    al_s = l_s + 64;

    const int tid  = threadIdx.x;
    const int lane = tid & 31;
    const int warp = tid >> 5;
    const int g    = lane >> 2;
    const int t    = lane & 3;
    const int wm   = warp & 3;
    const int wn   = warp >> 2;
    const int mBase = wm * 16;

    const int qt = blockIdx.x, h = blockIdx.y, b = blockIdx.z;
    const int q0 = qt * 64;

    const unsigned* Qg = g_q + (size_t)(b * NH + h) * LL * HD;
    const unsigned* Kg = g_k + (size_t)(b * NH + h) * LL * HD;
    const unsigned* Vg = g_v + (size_t)(b * NH + h) * LL * HD;

    // Q tile (plain loads; covered by first barrier)
    #pragma unroll
    for (int i = 0; i < 8; i++) {
        int idx = tid + i * 256;
        int row = idx >> 5;
        int c4  = (idx & 31) << 2;
        uint4 v = *(const uint4*)(Qg + (size_t)(q0 + row) * HD + c4);
        unsigned* d = Qs + row * QLD + c4;
        d[0] = v.x; d[1] = v.y; d[2] = v.z; d[3] = v.w;
    }
    if (tid < 64) { m_s[tid] = -1e30f; l_s[tid] = 0.f; }

    auto issue_kv = [&](int kt, int buf) {
        unsigned* Kd = Ks + buf * 64 * QLD;
        unsigned* Vd = Vs + buf * 64 * VLD;
        const unsigned* Kt = Kg + (size_t)kt * 64 * HD;
        const unsigned* Vt = Vg + (size_t)kt * 64 * HD;
        #pragma unroll
        for (int i = 0; i < 8; i++) {
            int idx = tid + i * 256;
            int row = idx >> 5;
            int c4  = (idx & 31) << 2;
            cp16(Kd + row * QLD + c4, Kt + row * HD + c4);
            cp16(Vd + row * VLD + c4, Vt + row * HD + c4);
        }
    };

    float o[8][4];
    #pragma unroll
    for (int nf = 0; nf < 8; nf++)
        #pragma unroll
        for (int r = 0; r < 4; r++) o[nf][r] = 0.f;

    const int ntiles = qt + 1;
    issue_kv(0, 0); CP_COMMIT();

    for (int kt = 0; kt < ntiles; kt++) {
        if (kt + 1 < ntiles) issue_kv(kt + 1, (kt + 1) & 1);
        CP_COMMIT();
        CP_WAIT(1);
        __syncthreads();

        const unsigned* Kb = Ks + (kt & 1) * 64 * QLD;
        const unsigned* Vb = Vs + (kt & 1) * 64 * VLD;
        const int kv0 = kt * 64;

        // S = Q K^T : warp tile 16 x 32
        float s[4][4];
        #pragma unroll
        for (int nf = 0; nf < 4; nf++)
            #pragma unroll
            for (int r = 0; r < 4; r++) s[nf][r] = 0.f;

        #pragma unroll
        for (int k = 0; k < 128; k += 8) {
            unsigned af[4];
            af[0] = Qs[(mBase + g)     * QLD + k + t];
            af[1] = Qs[(mBase + g + 8) * QLD + k + t];
            af[2] = Qs[(mBase + g)     * QLD + k + t + 4];
            af[3] = Qs[(mBase + g + 8) * QLD + k + t + 4];
            #pragma unroll
            for (int nf = 0; nf < 4; nf++) {
                int nb = wn * 32 + nf * 8;
                unsigned bf[2];
                bf[0] = Kb[(nb + g) * QLD + k + t];
                bf[1] = Kb[(nb + g) * QLD + k + t + 4];
                mma_tf32(s[nf], af, bf);
            }
        }

        // scale + causal mask -> Ps (raw float)
        const float sc = 0.08838834764831845f;
        #pragma unroll
        for (int nf = 0; nf < 4; nf++) {
            int nb = wn * 32 + nf * 8 + 2 * t;
            #pragma unroll
            for (int rr = 0; rr < 2; rr++) {
                int r    = mBase + g + rr * 8;
                int grow = q0 + r;
                #pragma unroll
                for (int cc = 0; cc < 2; cc++) {
                    int col = kv0 + nb + cc;
                    float v = s[nf][rr * 2 + cc] * sc;
                    if (col > grow) v = -1e30f;
                    Ps[r * PLD + nb + cc] = v;
                }
            }
        }
        __syncthreads();

        // online softmax: warp w owns rows w*8..w*8+7
        #pragma unroll
        for (int i = 0; i < 8; i++) {
            int r = warp * 8 + i;
            float v0 = Ps[r * PLD + lane];
            float v1 = Ps[r * PLD + lane + 32];
            float mx = fmaxf(v0, v1);
            #pragma unroll
            for (int off = 16; off; off >>= 1) mx = fmaxf(mx, __shfl_xor_sync(0xffffffffu, mx, off));
            float mold = m_s[r];
            float mnew = fmaxf(mold, mx);
            float al = __expf(mold - mnew);
            float p0 = __expf(v0 - mnew);
            float p1 = __expf(v1 - mnew);
            float sum = p0 + p1;
            #pragma unroll
            for (int off = 16; off; off >>= 1) sum += __shfl_xor_sync(0xffffffffu, sum, off);
            ((unsigned*)Ps)[r * PLD + lane]      = f2tf32(p0);
            ((unsigned*)Ps)[r * PLD + lane + 32] = f2tf32(p1);
            if (lane == 0) {
                l_s[r]  = al * l_s[r] + sum;
                m_s[r]  = mnew;
                al_s[r] = al;
            }
        }
        __syncthreads();

        // rescale O, O += P V (warp tile 16 x 64); V read column-wise
        float a0 = al_s[mBase + g];
        float a1 = al_s[mBase + g + 8];
        #pragma unroll
        for (int nf = 0; nf < 8; nf++) {
            o[nf][0] *= a0; o[nf][1] *= a0;
            o[nf][2] *= a1; o[nf][3] *= a1;
        }
        const unsigned* Pu = (const unsigned*)Ps;
        #pragma unroll
        for (int k = 0; k < 64; k += 8) {
            unsigned af[4];
            af[0] = Pu[(mBase + g)     * PLD + k + t];
            af[1] = Pu[(mBase + g + 8) * PLD + k + t];
            af[2] = Pu[(mBase + g)     * PLD + k + t + 4];
            af[3] = Pu[(mBase + g + 8) * PLD + k + t + 4];
            #pragma unroll
            for (int nf = 0; nf < 8; nf++) {
                int nb = wn * 64 + nf * 8;
                unsigned bf[2];
                bf[0] = Vb[(k + t)     * VLD + nb + g];
                bf[1] = Vb[(k + t + 4) * VLD + nb + g];
                mma_tf32(o[nf], af, bf);
            }
        }
        __syncthreads();   // protect buffers and Ps before next iteration
    }

    // finalize: O /= l, store tf32 bits to g_att [B,L,C]
    float li0 = 1.f / l_s[mBase + g];
    float li1 = 1.f / l_s[mBase + g + 8];
    #pragma unroll
    for (int nf = 0; nf < 8; nf++) {
        int col = h * HD + wn * 64 + nf * 8 + 2 * t;
        int r0  = q0 + mBase + g;
        int r1  = r0 + 8;
        size_t i0 = ((size_t)(b * LL + r0)) * CC + col;
        size_t i1 = ((size_t)(b * LL + r1)) * CC + col;
        g_att[i0]     = f2tf32(o[nf][0] * li0);
        g_att[i0 + 1] = f2tf32(o[nf][1] * li0);
        g_att[i1]     = f2tf32(o[nf][2] * li1);
        g_att[i1 + 1] = f2tf32(o[nf][3] * li1);
    }
}

// ---------------------------------------------------------------------------
// Launch
// ---------------------------------------------------------------------------
extern "C" void kernel_launch(void* const* d_in, const int* in_sizes, int n_in,
                              void* d_out, int out_size)
{
    (void)in_sizes; (void)out_size;
    const float* x    = (const float*)d_in[0];
    const float* rope = (const float*)d_in[1];
    const float* wq   = (const float*)d_in[n_in - 4];
    const float* wk   = (const float*)d_in[n_in - 3];
    const float* wv   = (const float*)d_in[n_in - 2];
    const float* wo   = (const float*)d_in[n_in - 1];
    float* out = (float*)d_out;

    static unsigned* xt_p = nullptr;
    // resolve device-global addresses (host-side; cudaGetSymbolAddress is capture-safe? use
    // cudaMemcpyToSymbol-free approach: kernels reference globals directly; converts need dst ptrs)
    unsigned *d_xt, *d_wq, *d_wk, *d_wv, *d_wo;
    cudaGetSymbolAddress((void**)&d_xt, g_xt);
    cudaGetSymbolAddress((void**)&d_wq, g_wq);
    cudaGetSymbolAddress((void**)&d_wk, g_wk);
    cudaGetSymbolAddress((void**)&d_wv, g_wv);
    cudaGetSymbolAddress((void**)&d_wo, g_wo);
    (void)xt_p;

    cudaFuncSetAttribute(gemm_kernel, cudaFuncAttributeMaxDynamicSharedMemorySize, GEMM_SMEM);
    cudaFuncSetAttribute(attn_kernel, cudaFuncAttributeMaxDynamicSharedMemorySize, ATT_SMEM);

    const int N4 = (int)((size_t)CC * KK / 4);   // 4194304
    dim3 cblk(256), cgrd((N4 + 255) / 256);
    cvt_kernel<<<cgrd, cblk>>>(x,  d_xt, N4);
    cvt_kernel<<<cgrd, cblk>>>(wq, d_wq, N4);
    cvt_kernel<<<cgrd, cblk>>>(wk, d_wk, N4);
    cvt_kernel<<<cgrd, cblk>>>(wv, d_wv, N4);
    cvt_kernel<<<cgrd, cblk>>>(wo, d_wo, N4);

    dim3 blk(256);
    // 1) QKV projections + RoPE (A = x tf32)
    gemm_kernel<<<dim3(CC / 128, MM / 256, 3), blk, GEMM_SMEM>>>(d_xt, rope, nullptr, 0);
    // 2) causal flash attention
    attn_kernel<<<dim3(LL / 64, NH, BB), blk, ATT_SMEM>>>();
    // 3) output projection (A = g_att tf32)
    unsigned* d_att;
    cudaGetSymbolAddress((void**)&d_att, g_att);
    gemm_kernel<<<dim3(CC / 128, MM / 256, 1), blk, GEMM_SMEM>>>(d_att, nullptr, out, 1);
}